// round 5
// baseline (speedup 1.0000x reference)
#include <cuda_runtime.h>
#include <cstdint>
#include <cstddef>

#define Bn 128
#define Tn 2048
#define Cn 128
#define NTHR 256
#define Wn 8           // warps per CTA
#define IW 16          // i-range per warp
#define TSTRIDE 132    // padded row stride for transposed transitions in smem

// Scratch: all forward alphas (exact fp32). __device__ global (no runtime alloc).
__device__ __align__(16) float g_alpha[(size_t)Bn * Tn * Cn];

__device__ __forceinline__ unsigned long long pack2(float lo, float hi) {
    unsigned long long r;
    asm("mov.b64 %0, {%1, %2};" : "=l"(r) : "f"(lo), "f"(hi));
    return r;
}
__device__ __forceinline__ unsigned long long add2(unsigned long long a, unsigned long long b) {
    unsigned long long r;
    asm("add.rn.f32x2 %0, %1, %2;" : "=l"(r) : "l"(a), "l"(b));
    return r;
}
__device__ __forceinline__ float lo32(unsigned long long v) {
    return __uint_as_float((unsigned)v);
}
__device__ __forceinline__ float hi32(unsigned long long v) {
    return __uint_as_float((unsigned)(v >> 32));
}

// Exact monotone float->int key (no NaNs in this data).
__device__ __forceinline__ int fkey(float f) {
    int b = __float_as_int(f);
    return b ^ ((b >> 31) & 0x7fffffff);
}

// Warp-collective argmax over 128 values (lane l holds indices 4l..4l+3).
// Returns SMALLEST index achieving the exact max (matches jnp.argmax).
__device__ __forceinline__ int warp_argmax4(float4 v, int l) {
    int k0 = fkey(v.x), k1 = fkey(v.y), k2 = fkey(v.z), k3 = fkey(v.w);
    int km = max(max(k0, k1), max(k2, k3));
    int wm = __reduce_max_sync(0xffffffffu, km);
    unsigned i0 = (k0 == wm) ? (unsigned)(4 * l + 0) : 0xffffffffu;
    unsigned i1 = (k1 == wm) ? (unsigned)(4 * l + 1) : 0xffffffffu;
    unsigned i2 = (k2 == wm) ? (unsigned)(4 * l + 2) : 0xffffffffu;
    unsigned i3 = (k3 == wm) ? (unsigned)(4 * l + 3) : 0xffffffffu;
    unsigned c = min(min(i0, i1), min(i2, i3));
    return (int)__reduce_min_sync(0xffffffffu, c);
}

__global__ __launch_bounds__(NTHR, 1)
void viterbi_kernel(const float* __restrict__ pot,
                    const float* __restrict__ trans,
                    float* __restrict__ out) {
    extern __shared__ float smem[];
    float* tT = smem;                          // [Cn][TSTRIDE] transposed transitions
    float* aRow = smem + Cn * TSTRIDE;         // [Cn] current alpha row (per-warp strips)
    float* pbuf = aRow + Cn;                   // [2][Wn][Cn] partial maxima (parity dbl-buf)

    const int b = blockIdx.x;
    const int tid = threadIdx.x;
    const int l = tid & 31;
    const int w = tid >> 5;        // warp id: i in [16w, 16w+16), reduces j in [16w, 16w+16)
    const int jr = 16 * w + (l >> 1);   // reduce-phase j
    const int h = l & 1;                // reduce-phase half (2 lanes per j)

    // ---- Build transposed transitions in smem (for backward) ----
    {
        int j0 = tid & 127;
        int r = tid >> 7;  // 0..1
        #pragma unroll
        for (int k = 0; k < 64; ++k) {
            int i = r * 64 + k;
            tT[j0 * TSTRIDE + i] = trans[i * Cn + j0];
        }
    }

    // ---- Per-thread transition regs: trP[jj*8+p] = (T[16w+2p, 4l+jj], T[16w+2p+1, 4l+jj]) ----
    unsigned long long trP[32];
    #pragma unroll
    for (int jj = 0; jj < 4; ++jj) {
        int j = 4 * l + jj;
        #pragma unroll
        for (int p = 0; p < 8; ++p) {
            int i = IW * w + 2 * p;
            trP[jj * 8 + p] = pack2(trans[i * Cn + j], trans[(i + 1) * Cn + j]);
        }
    }

    float* ab = g_alpha + (size_t)b * Tn * Cn;            // alpha rows for this batch
    const float* potj = pot + (size_t)b * Tn * Cn + jr;   // h0-lane potential stream

    // ---- t = 0 + pot prefetch ring (consumed at step t: slot t&3) ----
    float pr[4] = {0.f, 0.f, 0.f, 0.f};
    if (h == 0) {
        float a0 = potj[0];
        aRow[jr] = a0;
        ab[jr] = a0;
        pr[1] = potj[(size_t)1 * Cn];
        pr[2] = potj[(size_t)2 * Cn];
        pr[3] = potj[(size_t)3 * Cn];
        pr[0] = potj[(size_t)4 * Cn];
    }
    __syncthreads();

    const float NEG_INF = __int_as_float(0xff800000);

    // ---- Forward: t = 1 .. T-1 (one alternating named barrier per step) ----
    for (int t = 1; t < Tn; ++t) {
        const int par = t & 1;

        // A-phase: partial max over own i-strip for j = 4l..4l+3
        const ulonglong2* as = (const ulonglong2*)(aRow + w * IW);
        float m0 = NEG_INF, m1 = NEG_INF, m2 = NEG_INF, m3 = NEG_INF;
        #pragma unroll
        for (int g = 0; g < 4; ++g) {
            ulonglong2 A = as[g];   // broadcast LDS.128: alpha[16w+4g .. +3]
            unsigned long long s0, s1;
            s0 = add2(A.x, trP[0 * 8 + 2 * g]);
            s1 = add2(A.y, trP[0 * 8 + 2 * g + 1]);
            m0 = fmaxf(fmaxf(m0, lo32(s0)), fmaxf(hi32(s0), fmaxf(lo32(s1), hi32(s1))));
            s0 = add2(A.x, trP[1 * 8 + 2 * g]);
            s1 = add2(A.y, trP[1 * 8 + 2 * g + 1]);
            m1 = fmaxf(fmaxf(m1, lo32(s0)), fmaxf(hi32(s0), fmaxf(lo32(s1), hi32(s1))));
            s0 = add2(A.x, trP[2 * 8 + 2 * g]);
            s1 = add2(A.y, trP[2 * 8 + 2 * g + 1]);
            m2 = fmaxf(fmaxf(m2, lo32(s0)), fmaxf(hi32(s0), fmaxf(lo32(s1), hi32(s1))));
            s0 = add2(A.x, trP[3 * 8 + 2 * g]);
            s1 = add2(A.y, trP[3 * 8 + 2 * g + 1]);
            m3 = fmaxf(fmaxf(m3, lo32(s0)), fmaxf(hi32(s0), fmaxf(lo32(s1), hi32(s1))));
        }
        // store partials for j = 4l..4l+3
        float4 pv = make_float4(m0, m1, m2, m3);
        ((float4*)(pbuf + ((size_t)par * Wn + w) * Cn))[l] = pv;

        // one block barrier, alternating id (skew-proof with pbuf parity)
        asm volatile("bar.sync %0, %1;" :: "r"(1 + par), "r"(NTHR) : "memory");

        // R-phase: reduce 8 partials for j = jr (2 lanes/j)
        const float* pb = pbuf + (size_t)par * Wn * Cn;
        float p0 = pb[(4 * h + 0) * Cn + jr];
        float p1 = pb[(4 * h + 1) * Cn + jr];
        float p2 = pb[(4 * h + 2) * Cn + jr];
        float p3 = pb[(4 * h + 3) * Cn + jr];
        float mm = fmaxf(fmaxf(p0, p1), fmaxf(p2, p3));
        mm = fmaxf(mm, __shfl_xor_sync(0xffffffffu, mm, 1));
        if (h == 0) {
            float al = mm + pr[t & 3];
            if (t + 4 < Tn) pr[t & 3] = potj[(size_t)(t + 4) * Cn];
            aRow[jr] = al;                       // own-warp strip (j in [16w,16w+16))
            ab[(size_t)t * Cn + jr] = al;        // for backward
        }
        __syncwarp();
    }

    __syncthreads();  // aRow + g_alpha STGs visible CTA-wide

    // ---- Backward: warp 0 traces the path (transitions from smem) ----
    if (tid < 32) {
        float* ob = out + (size_t)b * Tn;

        const float4* ar4 = (const float4*)aRow;
        float4 av = ar4[l];
        int tag = warp_argmax4(av, l);
        if (l == 0) ob[Tn - 1] = (float)tag;

        const float4* arow = (const float4*)(g_alpha + (size_t)b * Tn * Cn);

        // Prefetch alpha rows 8 deep (independent of the tag chain)
        float4 pf[8];
        const int t0 = Tn - 2;
        #pragma unroll
        for (int u = 0; u < 8; ++u) {
            pf[u] = (t0 - u >= 0) ? arow[(size_t)(t0 - u) * 32 + l]
                                  : make_float4(0.f, 0.f, 0.f, 0.f);
        }

        for (int tb = t0; tb >= 0; tb -= 8) {
            #pragma unroll
            for (int u = 0; u < 8; ++u) {
                int t = tb - u;
                if (t >= 0) {
                    float4 a = pf[u];
                    if (t - 8 >= 0) pf[u] = arow[(size_t)(t - 8) * 32 + l];

                    const float4* trow = (const float4*)(tT + tag * TSTRIDE);
                    float4 tv = trow[l];
                    float4 s;
                    s.x = a.x + tv.x;
                    s.y = a.y + tv.y;
                    s.z = a.z + tv.z;
                    s.w = a.w + tv.w;
                    tag = warp_argmax4(s, l);
                    if (l == 0) ob[t] = (float)tag;
                }
            }
        }
    }
}

extern "C" void kernel_launch(void* const* d_in, const int* in_sizes, int n_in,
                              void* d_out, int out_size) {
    const float* inputs = (const float*)d_in[0];       // [B, T, C] f32
    const float* transitions = (const float*)d_in[1];  // [C, C] f32
    float* out = (float*)d_out;                        // [B, T] f32 (tags)

    const int smem_bytes = (Cn * TSTRIDE + Cn + 2 * Wn * Cn) * (int)sizeof(float);  // ~74.5KB
    cudaFuncSetAttribute(viterbi_kernel, cudaFuncAttributeMaxDynamicSharedMemorySize, smem_bytes);
    viterbi_kernel<<<Bn, NTHR, smem_bytes>>>(inputs, transitions, out);
}

// round 6
// speedup vs baseline: 1.0830x; 1.0830x over previous
#include <cuda_runtime.h>
#include <cstdint>
#include <cstddef>

#define Bn 128
#define Tn 2048
#define Cn 128
#define NTHR 512
#define TSTRIDE 132  // padded row stride for transposed transitions in smem (backward)

// Scratch: all forward alphas (exact fp32). __device__ global (no runtime alloc).
__device__ __align__(16) float g_alpha[(size_t)Bn * Tn * Cn];

__device__ __forceinline__ unsigned long long pack2(float lo, float hi) {
    unsigned long long r;
    asm("mov.b64 %0, {%1, %2};" : "=l"(r) : "f"(lo), "f"(hi));
    return r;
}
__device__ __forceinline__ unsigned long long add2(unsigned long long a, unsigned long long b) {
    unsigned long long r;
    asm("add.rn.f32x2 %0, %1, %2;" : "=l"(r) : "l"(a), "l"(b));
    return r;
}
__device__ __forceinline__ float lo32(unsigned long long v) {
    return __uint_as_float((unsigned)v);
}
__device__ __forceinline__ float hi32(unsigned long long v) {
    return __uint_as_float((unsigned)(v >> 32));
}

// Exact monotone float->int key (no NaNs in this data).
__device__ __forceinline__ int fkey(float f) {
    int b = __float_as_int(f);
    return b ^ ((b >> 31) & 0x7fffffff);
}

// Warp-collective argmax over 128 values (lane l holds indices 4l..4l+3).
// Returns SMALLEST index achieving the exact max (matches jnp.argmax).
__device__ __forceinline__ int warp_argmax4(float4 v, int l) {
    int k0 = fkey(v.x), k1 = fkey(v.y), k2 = fkey(v.z), k3 = fkey(v.w);
    int km = max(max(k0, k1), max(k2, k3));
    int wm = __reduce_max_sync(0xffffffffu, km);
    unsigned i0 = (k0 == wm) ? (unsigned)(4 * l + 0) : 0xffffffffu;
    unsigned i1 = (k1 == wm) ? (unsigned)(4 * l + 1) : 0xffffffffu;
    unsigned i2 = (k2 == wm) ? (unsigned)(4 * l + 2) : 0xffffffffu;
    unsigned i3 = (k3 == wm) ? (unsigned)(4 * l + 3) : 0xffffffffu;
    unsigned c = min(min(i0, i1), min(i2, i3));
    return (int)__reduce_min_sync(0xffffffffu, c);
}

// ============================ FORWARD ============================
__global__ __launch_bounds__(NTHR, 1)
void viterbi_fwd(const float* __restrict__ pot,
                 const float* __restrict__ trans) {
    __shared__ __align__(16) float sb[2][Cn];  // double-buffered alpha row

    const int b = blockIdx.x;
    const int tid = threadIdx.x;
    const int c = tid & 3;    // i-chunk within quad
    const int j = tid >> 2;   // class handled by this thread-quad

    // Per-thread transition regs: i = 16g + 4c + {0..3}, column j, packed.
    unsigned long long tr2[16];
    #pragma unroll
    for (int g = 0; g < 8; ++g) {
        int i0 = 16 * g + 4 * c;
        float t0 = trans[(i0 + 0) * Cn + j];
        float t1 = trans[(i0 + 1) * Cn + j];
        float t2 = trans[(i0 + 2) * Cn + j];
        float t3 = trans[(i0 + 3) * Cn + j];
        tr2[2 * g]     = pack2(t0, t1);
        tr2[2 * g + 1] = pack2(t2, t3);
    }

    const float* potp = pot + (size_t)b * Tn * Cn + j;
    float* aout = g_alpha + (size_t)b * Tn * Cn + j;

    // t = 0
    float alpha = 0.f;
    if (c == 0) {
        alpha = potp[0];
        sb[0][j] = alpha;
        aout[0] = alpha;
    }

    // Potentials prefetch ring (distance 4), only c<2 lanes participate.
    float pr[4] = {0.f, 0.f, 0.f, 0.f};
    if (c < 2) {
        pr[1] = potp[(size_t)1 * Cn];
        pr[2] = potp[(size_t)2 * Cn];
        pr[3] = potp[(size_t)3 * Cn];
        pr[0] = potp[(size_t)4 * Cn];
    }

    __syncthreads();

    int p = 0;
    for (int t = 1; t < Tn; ++t) {
        float potv = pr[t & 3];
        if (c < 2 && t + 4 < Tn) pr[t & 3] = potp[(size_t)(t + 4) * Cn];

        const ulonglong2* ab = (const ulonglong2*)sb[p];
        float g0[8];
        #pragma unroll
        for (int g = 0; g < 8; ++g) {
            ulonglong2 a = ab[4 * g + c];  // 16B: alpha[16g+4c .. +3]
            unsigned long long s01 = add2(a.x, tr2[2 * g]);
            unsigned long long s23 = add2(a.y, tr2[2 * g + 1]);
            g0[g] = fmaxf(fmaxf(lo32(s01), hi32(s01)), fmaxf(lo32(s23), hi32(s23)));
        }
        // shallow tree over 8 group maxima
        float h0 = fmaxf(g0[0], g0[1]);
        float h1 = fmaxf(g0[2], g0[3]);
        float h2 = fmaxf(g0[4], g0[5]);
        float h3 = fmaxf(g0[6], g0[7]);
        float best = fmaxf(fmaxf(h0, h1), fmaxf(h2, h3));
        // butterfly: ALL 4 c-lanes end with the full max
        best = fmaxf(best, __shfl_xor_sync(0xffffffffu, best, 1));
        best = fmaxf(best, __shfl_xor_sync(0xffffffffu, best, 2));

        alpha = best + potv;               // valid on c<2 lanes
        if (c == 0) sb[p ^ 1][j] = alpha;  // smem row for next step
        if (c == 1) aout[(size_t)t * Cn] = alpha;  // gmem archive (off c==0 path)
        __syncthreads();
        p ^= 1;
    }
}

// ============================ BACKWARD ============================
__global__ __launch_bounds__(128, 1)
void viterbi_bwd(const float* __restrict__ trans,
                 float* __restrict__ out) {
    extern __shared__ float tT[];  // [Cn][TSTRIDE]: tT[j*TSTRIDE + i] = trans[i][j]

    const int b = blockIdx.x;
    const int tid = threadIdx.x;

    // Build transposed transitions in smem (coalesced reads across tid).
    {
        int j0 = tid;  // 0..127
        #pragma unroll 8
        for (int i = 0; i < Cn; ++i) {
            tT[j0 * TSTRIDE + i] = trans[i * Cn + j0];
        }
    }
    __syncthreads();

    if (tid < 32) {
        const int l = tid;
        float* ob = out + (size_t)b * Tn;
        const float4* arow = (const float4*)(g_alpha + (size_t)b * Tn * Cn);

        // last tag = argmax over alpha_{T-1}
        float4 av = arow[(size_t)(Tn - 1) * 32 + l];
        int tag = warp_argmax4(av, l);
        if (l == 0) ob[Tn - 1] = (float)tag;

        // Prefetch alpha rows 8 deep (independent of the tag chain)
        float4 pf[8];
        const int t0 = Tn - 2;
        #pragma unroll
        for (int u = 0; u < 8; ++u) {
            pf[u] = (t0 - u >= 0) ? arow[(size_t)(t0 - u) * 32 + l]
                                  : make_float4(0.f, 0.f, 0.f, 0.f);
        }

        for (int tb = t0; tb >= 0; tb -= 8) {
            #pragma unroll
            for (int u = 0; u < 8; ++u) {
                int t = tb - u;
                if (t >= 0) {
                    float4 a = pf[u];
                    if (t - 8 >= 0) pf[u] = arow[(size_t)(t - 8) * 32 + l];

                    const float4* trow = (const float4*)(tT + tag * TSTRIDE);
                    float4 tv = trow[l];
                    float4 s;
                    s.x = a.x + tv.x;
                    s.y = a.y + tv.y;
                    s.z = a.z + tv.z;
                    s.w = a.w + tv.w;
                    tag = warp_argmax4(s, l);
                    if (l == 0) ob[t] = (float)tag;
                }
            }
        }
    }
}

extern "C" void kernel_launch(void* const* d_in, const int* in_sizes, int n_in,
                              void* d_out, int out_size) {
    const float* inputs = (const float*)d_in[0];       // [B, T, C] f32
    const float* transitions = (const float*)d_in[1];  // [C, C] f32
    float* out = (float*)d_out;                        // [B, T] f32 (tags)

    viterbi_fwd<<<Bn, NTHR>>>(inputs, transitions);

    const int bwd_smem = Cn * TSTRIDE * (int)sizeof(float);  // ~67.6KB
    cudaFuncSetAttribute(viterbi_bwd, cudaFuncAttributeMaxDynamicSharedMemorySize, bwd_smem);
    viterbi_bwd<<<Bn, 128, bwd_smem>>>(transitions, out);
}

// round 7
// speedup vs baseline: 1.0991x; 1.0149x over previous
#include <cuda_runtime.h>
#include <cstdint>
#include <cstddef>

#define Bn 128
#define Tn 2048
#define Cn 128
#define NTHR 512
#define TSTRIDE 132  // padded row stride for transposed transitions in smem (backward)

// Scratch: all forward alphas (exact fp32). __device__ global (no runtime alloc).
__device__ __align__(16) float g_alpha[(size_t)Bn * Tn * Cn];

__device__ __forceinline__ unsigned long long pack2(float lo, float hi) {
    unsigned long long r;
    asm("mov.b64 %0, {%1, %2};" : "=l"(r) : "f"(lo), "f"(hi));
    return r;
}
__device__ __forceinline__ unsigned long long add2(unsigned long long a, unsigned long long b) {
    unsigned long long r;
    asm("add.rn.f32x2 %0, %1, %2;" : "=l"(r) : "l"(a), "l"(b));
    return r;
}
__device__ __forceinline__ float lo32(unsigned long long v) {
    return __uint_as_float((unsigned)v);
}
__device__ __forceinline__ float hi32(unsigned long long v) {
    return __uint_as_float((unsigned)(v >> 32));
}

// Exact monotone float->int key (no NaNs in this data).
__device__ __forceinline__ int fkey(float f) {
    int b = __float_as_int(f);
    return b ^ ((b >> 31) & 0x7fffffff);
}

// Warp-collective argmax over 128 values (lane l holds indices 4l..4l+3)
// using ONLY shfl/vote (no REDUX). Returns SMALLEST index achieving the max.
__device__ __forceinline__ int warp_argmax4_shfl(float4 v, int l) {
    int k0 = fkey(v.x), k1 = fkey(v.y), k2 = fkey(v.z), k3 = fkey(v.w);
    int km = max(max(k0, k1), max(k2, k3));

    // 5-level butterfly max (each level: SHFL ~26 + IMNMX ~4)
    int wm = km;
    wm = max(wm, __shfl_xor_sync(0xffffffffu, wm, 16));
    wm = max(wm, __shfl_xor_sync(0xffffffffu, wm, 8));
    wm = max(wm, __shfl_xor_sync(0xffffffffu, wm, 4));
    wm = max(wm, __shfl_xor_sync(0xffffffffu, wm, 2));
    wm = max(wm, __shfl_xor_sync(0xffffffffu, wm, 1));

    // Lane-local first slot equal to km — independent of wm (off critical path).
    int loc = (k0 == km) ? 0 : ((k1 == km) ? 1 : ((k2 == km) ? 2 : 3));

    // First lane whose local max equals the warp max; then its first local slot.
    unsigned ball = __ballot_sync(0xffffffffu, km == wm);
    int lane = __ffs(ball) - 1;
    int locw = __shfl_sync(0xffffffffu, loc, lane);
    return 4 * lane + locw;
}

// ============================ FORWARD ============================
__global__ __launch_bounds__(NTHR, 1)
void viterbi_fwd(const float* __restrict__ pot,
                 const float* __restrict__ trans) {
    __shared__ __align__(16) float sb[2][Cn];  // double-buffered alpha row

    const int b = blockIdx.x;
    const int tid = threadIdx.x;
    const int c = tid & 3;    // i-chunk within quad
    const int j = tid >> 2;   // class handled by this thread-quad

    // Per-thread transition regs: i = 16g + 4c + {0..3}, column j, packed.
    unsigned long long tr2[16];
    #pragma unroll
    for (int g = 0; g < 8; ++g) {
        int i0 = 16 * g + 4 * c;
        float t0 = trans[(i0 + 0) * Cn + j];
        float t1 = trans[(i0 + 1) * Cn + j];
        float t2 = trans[(i0 + 2) * Cn + j];
        float t3 = trans[(i0 + 3) * Cn + j];
        tr2[2 * g]     = pack2(t0, t1);
        tr2[2 * g + 1] = pack2(t2, t3);
    }

    const float* potp = pot + (size_t)b * Tn * Cn + j;
    float* aout = g_alpha + (size_t)b * Tn * Cn + j;

    // t = 0
    float alpha = 0.f;
    if (c == 0) {
        alpha = potp[0];
        sb[0][j] = alpha;
        aout[0] = alpha;
    }

    // Potentials prefetch ring (distance 4), only c<2 lanes participate.
    float pr[4] = {0.f, 0.f, 0.f, 0.f};
    if (c < 2) {
        pr[1] = potp[(size_t)1 * Cn];
        pr[2] = potp[(size_t)2 * Cn];
        pr[3] = potp[(size_t)3 * Cn];
        pr[0] = potp[(size_t)4 * Cn];
    }

    __syncthreads();

    int p = 0;
    for (int t = 1; t < Tn; ++t) {
        float potv = pr[t & 3];
        if (c < 2 && t + 4 < Tn) pr[t & 3] = potp[(size_t)(t + 4) * Cn];

        const ulonglong2* ab = (const ulonglong2*)sb[p];
        float g0[8];
        #pragma unroll
        for (int g = 0; g < 8; ++g) {
            ulonglong2 a = ab[4 * g + c];  // 16B: alpha[16g+4c .. +3]
            unsigned long long s01 = add2(a.x, tr2[2 * g]);
            unsigned long long s23 = add2(a.y, tr2[2 * g + 1]);
            g0[g] = fmaxf(fmaxf(lo32(s01), hi32(s01)), fmaxf(lo32(s23), hi32(s23)));
        }
        // shallow tree over 8 group maxima
        float h0 = fmaxf(g0[0], g0[1]);
        float h1 = fmaxf(g0[2], g0[3]);
        float h2 = fmaxf(g0[4], g0[5]);
        float h3 = fmaxf(g0[6], g0[7]);
        float best = fmaxf(fmaxf(h0, h1), fmaxf(h2, h3));
        // butterfly: c-lanes 0/1 end with the full max
        best = fmaxf(best, __shfl_xor_sync(0xffffffffu, best, 1));
        best = fmaxf(best, __shfl_xor_sync(0xffffffffu, best, 2));

        alpha = best + potv;               // valid on c<2 lanes
        if (c == 0) sb[p ^ 1][j] = alpha;  // smem row for next step
        if (c == 1) aout[(size_t)t * Cn] = alpha;  // gmem archive (off c==0 path)
        __syncthreads();
        p ^= 1;
    }
}

// ============================ BACKWARD ============================
__global__ __launch_bounds__(128, 1)
void viterbi_bwd(const float* __restrict__ trans,
                 float* __restrict__ out) {
    extern __shared__ float tT[];  // [Cn][TSTRIDE]: tT[j*TSTRIDE + i] = trans[i][j]

    const int b = blockIdx.x;
    const int tid = threadIdx.x;

    // Build transposed transitions in smem (coalesced reads across tid).
    {
        int j0 = tid;  // 0..127
        #pragma unroll 8
        for (int i = 0; i < Cn; ++i) {
            tT[j0 * TSTRIDE + i] = trans[i * Cn + j0];
        }
    }
    __syncthreads();

    if (tid < 32) {
        const int l = tid;
        float* ob = out + (size_t)b * Tn;
        const float4* arow = (const float4*)(g_alpha + (size_t)b * Tn * Cn);

        // last tag = argmax over alpha_{T-1}
        float4 av = arow[(size_t)(Tn - 1) * 32 + l];
        int tag = warp_argmax4_shfl(av, l);
        if (l == 0) ob[Tn - 1] = (float)tag;

        // Prefetch alpha rows 8 deep (independent of the tag chain)
        float4 pf[8];
        const int t0 = Tn - 2;
        #pragma unroll
        for (int u = 0; u < 8; ++u) {
            pf[u] = (t0 - u >= 0) ? arow[(size_t)(t0 - u) * 32 + l]
                                  : make_float4(0.f, 0.f, 0.f, 0.f);
        }

        for (int tb = t0; tb >= 0; tb -= 8) {
            #pragma unroll
            for (int u = 0; u < 8; ++u) {
                int t = tb - u;
                if (t >= 0) {
                    float4 a = pf[u];
                    if (t - 8 >= 0) pf[u] = arow[(size_t)(t - 8) * 32 + l];

                    const float4* trow = (const float4*)(tT + tag * TSTRIDE);
                    float4 tv = trow[l];
                    float4 s;
                    s.x = a.x + tv.x;
                    s.y = a.y + tv.y;
                    s.z = a.z + tv.z;
                    s.w = a.w + tv.w;
                    tag = warp_argmax4_shfl(s, l);
                    if (l == 0) ob[t] = (float)tag;
                }
            }
        }
    }
}

extern "C" void kernel_launch(void* const* d_in, const int* in_sizes, int n_in,
                              void* d_out, int out_size) {
    const float* inputs = (const float*)d_in[0];       // [B, T, C] f32
    const float* transitions = (const float*)d_in[1];  // [C, C] f32
    float* out = (float*)d_out;                        // [B, T] f32 (tags)

    viterbi_fwd<<<Bn, NTHR>>>(inputs, transitions);

    const int bwd_smem = Cn * TSTRIDE * (int)sizeof(float);  // ~67.6KB
    cudaFuncSetAttribute(viterbi_bwd, cudaFuncAttributeMaxDynamicSharedMemorySize, bwd_smem);
    viterbi_bwd<<<Bn, 128, bwd_smem>>>(transitions, out);
}

// round 8
// speedup vs baseline: 1.7092x; 1.5551x over previous
#include <cuda_runtime.h>
#include <cstdint>
#include <cstddef>

#define Bn 128
#define Tn 2048
#define Cn 128
#define NTHR 512
#define TSTRIDE 132  // padded row stride for transposed transitions in smem (backward)

// Scratch: all forward alphas (exact fp32). __device__ global (no runtime alloc).
__device__ __align__(16) float g_alpha[(size_t)Bn * Tn * Cn];

__device__ __forceinline__ unsigned long long pack2(float lo, float hi) {
    unsigned long long r;
    asm("mov.b64 %0, {%1, %2};" : "=l"(r) : "f"(lo), "f"(hi));
    return r;
}
__device__ __forceinline__ unsigned long long add2(unsigned long long a, unsigned long long b) {
    unsigned long long r;
    asm("add.rn.f32x2 %0, %1, %2;" : "=l"(r) : "l"(a), "l"(b));
    return r;
}
__device__ __forceinline__ float lo32(unsigned long long v) {
    return __uint_as_float((unsigned)v);
}
__device__ __forceinline__ float hi32(unsigned long long v) {
    return __uint_as_float((unsigned)(v >> 32));
}

// Exact monotone float->int key (no NaNs in this data).
__device__ __forceinline__ int fkey(float f) {
    int b = __float_as_int(f);
    return b ^ ((b >> 31) & 0x7fffffff);
}

// Warp-collective argmax over 128 values (lane l holds indices 4l..4l+3)
// using ONLY shfl/vote. Returns SMALLEST index achieving the max.
__device__ __forceinline__ int warp_argmax4_shfl(float4 v, int l) {
    int k0 = fkey(v.x), k1 = fkey(v.y), k2 = fkey(v.z), k3 = fkey(v.w);
    int km = max(max(k0, k1), max(k2, k3));

    int wm = km;
    wm = max(wm, __shfl_xor_sync(0xffffffffu, wm, 16));
    wm = max(wm, __shfl_xor_sync(0xffffffffu, wm, 8));
    wm = max(wm, __shfl_xor_sync(0xffffffffu, wm, 4));
    wm = max(wm, __shfl_xor_sync(0xffffffffu, wm, 2));
    wm = max(wm, __shfl_xor_sync(0xffffffffu, wm, 1));

    // Lane-local first slot equal to km (independent of wm: off critical path).
    int loc = (k0 == km) ? 0 : ((k1 == km) ? 1 : ((k2 == km) ? 2 : 3));

    unsigned ball = __ballot_sync(0xffffffffu, km == wm);
    int lane = __ffs(ball) - 1;
    int locw = __shfl_sync(0xffffffffu, loc, lane);
    return 4 * lane + locw;
}

// ============================ FORWARD ============================
__global__ __launch_bounds__(NTHR, 1)
void viterbi_fwd(const float* __restrict__ pot,
                 const float* __restrict__ trans) {
    __shared__ __align__(16) float sb[2][Cn];  // double-buffered alpha row

    const int b = blockIdx.x;
    const int tid = threadIdx.x;
    const int c = tid & 3;    // i-chunk within quad
    const int j = tid >> 2;   // class handled by this thread-quad

    // Per-thread transition regs: i = 16g + 4c + {0..3}, column j, packed.
    unsigned long long tr2[16];
    #pragma unroll
    for (int g = 0; g < 8; ++g) {
        int i0 = 16 * g + 4 * c;
        float t0 = trans[(i0 + 0) * Cn + j];
        float t1 = trans[(i0 + 1) * Cn + j];
        float t2 = trans[(i0 + 2) * Cn + j];
        float t3 = trans[(i0 + 3) * Cn + j];
        tr2[2 * g]     = pack2(t0, t1);
        tr2[2 * g + 1] = pack2(t2, t3);
    }

    const float* potp = pot + (size_t)b * Tn * Cn + j;
    float* aout = g_alpha + (size_t)b * Tn * Cn + j;

    // t = 0
    if (c == 0) {
        float a0 = potp[0];
        sb[0][j] = a0;
        aout[0] = a0;
    }

    // Potentials prefetch ring (distance 4); only c<2 lanes participate
    // (thread-invariant predicate -> @P LDG, no branch region).
    const bool pfl = (c < 2);
    float pr[4] = {0.f, 0.f, 0.f, 0.f};
    if (pfl) {
        pr[1] = potp[(size_t)1 * Cn];
        pr[2] = potp[(size_t)2 * Cn];
        pr[3] = potp[(size_t)3 * Cn];
        pr[0] = potp[(size_t)4 * Cn];
    }

    __syncthreads();

    int p = 0;

    // One branch-free step. PF: compile-time prefetch switch.
    auto step = [&](int t, bool PF) {
        float potv = pr[t & 3];
        if (PF && pfl) {
            int idx = min(t + 4, Tn - 1);                 // clamp: no guard branch
            pr[t & 3] = potp[(size_t)idx * Cn];
        }

        const ulonglong2* ab = (const ulonglong2*)sb[p];
        float g0[8];
        #pragma unroll
        for (int g = 0; g < 8; ++g) {
            ulonglong2 a = ab[4 * g + c];  // 16B: alpha[16g+4c .. +3]
            unsigned long long s01 = add2(a.x, tr2[2 * g]);
            unsigned long long s23 = add2(a.y, tr2[2 * g + 1]);
            g0[g] = fmaxf(fmaxf(lo32(s01), hi32(s01)), fmaxf(lo32(s23), hi32(s23)));
        }
        float h0 = fmaxf(g0[0], g0[1]);
        float h1 = fmaxf(g0[2], g0[3]);
        float h2 = fmaxf(g0[4], g0[5]);
        float h3 = fmaxf(g0[6], g0[7]);
        float best = fmaxf(fmaxf(h0, h1), fmaxf(h2, h3));
        best = fmaxf(best, __shfl_xor_sync(0xffffffffu, best, 1));
        best = fmaxf(best, __shfl_xor_sync(0xffffffffu, best, 2));

        float alpha = best + potv;
        if (c == 0) sb[p ^ 1][j] = alpha;           // @P STS
        if (c == 1) aout[(size_t)t * Cn] = alpha;   // @P STG (off the STS lane)
        __syncthreads();
        p ^= 1;
    };

    // Main: t = 1 .. 2044 (511 blocks of 4, branch-free).
    for (int tb = 1; tb <= Tn - 7; tb += 4) {
        step(tb + 0, true);
        step(tb + 1, true);
        step(tb + 2, true);
        step(tb + 3, true);
    }
    // Tail: t = 2045, 2046, 2047 (no prefetch).
    step(Tn - 3, false);
    step(Tn - 2, false);
    step(Tn - 1, false);
}

// ============================ BACKWARD ============================
__global__ __launch_bounds__(128, 1)
void viterbi_bwd(const float* __restrict__ trans,
                 float* __restrict__ out) {
    extern __shared__ float tT[];  // [Cn][TSTRIDE]: tT[j*TSTRIDE + i] = trans[i][j]

    const int b = blockIdx.x;
    const int tid = threadIdx.x;

    // Build transposed transitions in smem (coalesced reads across tid).
    {
        int j0 = tid;  // 0..127
        #pragma unroll 8
        for (int i = 0; i < Cn; ++i) {
            tT[j0 * TSTRIDE + i] = trans[i * Cn + j0];
        }
    }
    __syncthreads();

    if (tid < 32) {
        const int l = tid;
        float* ob = out + (size_t)b * Tn;
        const float4* arow = (const float4*)(g_alpha + (size_t)b * Tn * Cn);

        // last tag = argmax over alpha_{T-1}
        float4 av = arow[(size_t)(Tn - 1) * 32 + l];
        int tag = warp_argmax4_shfl(av, l);
        if (l == 0) ob[Tn - 1] = (float)tag;

        // Prefetch alpha rows 8 deep: pf[u] = row (2046 - u).
        float4 pf[8];
        #pragma unroll
        for (int u = 0; u < 8; ++u) {
            pf[u] = arow[(size_t)(Tn - 2 - u) * 32 + l];
        }

        // One trace step; PF: unconditional prefetch of row t-8 (caller guarantees
        // t-8 >= 0 when PF=true; when PF=false, CLAMPED prefetch keeps it branch-free).
        auto tstep = [&](int t, int u, bool PF) {
            float4 a = pf[u];
            if (PF) {
                pf[u] = arow[(size_t)(t - 8) * 32 + l];
            } else {
                int idx = max(t - 8, 0);                 // clamp: no guard branch
                pf[u] = arow[(size_t)idx * 32 + l];
            }
            const float4* trow = (const float4*)(tT + tag * TSTRIDE);
            float4 tv = trow[l];
            float4 s;
            s.x = a.x + tv.x;
            s.y = a.y + tv.y;
            s.z = a.z + tv.z;
            s.w = a.w + tv.w;
            tag = warp_argmax4_shfl(s, l);
            if (l == 0) ob[t] = (float)tag;              // @P STG
        };

        // Main: t = 2046 .. 15 (254 blocks of 8, fully branch-free).
        for (int tb = Tn - 2; tb >= 22; tb -= 8) {
            #pragma unroll
            for (int u = 0; u < 8; ++u) {
                tstep(tb - u, u, true);
            }
        }
        // Tail A: t = 14 .. 7 (clamped prefetch fills rows 6..0 into pf[0..6]).
        #pragma unroll
        for (int u = 0; u < 8; ++u) {
            tstep(14 - u, u, false);
        }
        // Tail B: t = 6 .. 0 (no prefetch needed; pf[0..6] hold rows 6..0).
        #pragma unroll
        for (int u = 0; u < 7; ++u) {
            int t = 6 - u;
            float4 a = pf[u];
            const float4* trow = (const float4*)(tT + tag * TSTRIDE);
            float4 tv = trow[l];
            float4 s;
            s.x = a.x + tv.x;
            s.y = a.y + tv.y;
            s.z = a.z + tv.z;
            s.w = a.w + tv.w;
            tag = warp_argmax4_shfl(s, l);
            if (l == 0) ob[t] = (float)tag;
        }
    }
}

extern "C" void kernel_launch(void* const* d_in, const int* in_sizes, int n_in,
                              void* d_out, int out_size) {
    const float* inputs = (const float*)d_in[0];       // [B, T, C] f32
    const float* transitions = (const float*)d_in[1];  // [C, C] f32
    float* out = (float*)d_out;                        // [B, T] f32 (tags)

    viterbi_fwd<<<Bn, NTHR>>>(inputs, transitions);

    const int bwd_smem = Cn * TSTRIDE * (int)sizeof(float);  // ~67.6KB
    cudaFuncSetAttribute(viterbi_bwd, cudaFuncAttributeMaxDynamicSharedMemorySize, bwd_smem);
    viterbi_bwd<<<Bn, 128, bwd_smem>>>(transitions, out);
}